// round 3
// baseline (speedup 1.0000x reference)
#include <cuda_runtime.h>
#include <cstdint>

#define BATCH 16
#define MAXGT 64
#define NCLS 80
#define HWTOT 21824
#define NLVL 5
#define NTILES 86                 // tiles per image: 64+16+4+1+1
#define UNITS (NTILES * BATCH)    // 1376
#define GRID_MAIN 1184            // 8 blocks/SM * 148 SMs

// Output layout (floats), concatenated in reference return order.
#define OFF_CLS_T 0ULL
#define OFF_CLS_M ((size_t)BATCH * HWTOT * NCLS)            // 27,934,720
#define OFF_NP    (OFF_CLS_M + (size_t)BATCH * HWTOT)       // 28,283,904
#define OFF_REG_T (OFF_NP + BATCH)                          // 28,283,920
#define OFF_REG_M (OFF_REG_T + (size_t)BATCH * HWTOT * 4)   // 29,680,656

struct __align__(16) GtEntry {    // 96 B
    int4   pos;   // x1,y1,x2,y2 pos region (feature coords)
    int4   ign;   // ignore region
    int4   uni;   // union bbox for warp skip test
    float4 box;   // image-coord box
    float  area;
    int    lab;
    int    pad0, pad1;
};

__device__ float    d_np[BATCH];            // zero-init; reset each replay
__device__ unsigned d_wctr   = GRID_MAIN;   // work-steal counter; reset each replay
__device__ unsigned d_ticket = 0;           // completion ticket; reset each replay

// Shrunken/clipped region bounds exactly like reference _prop_box.
// __f*_rn intrinsics forbid FMA contraction (floor/ceil boundary safety).
static __device__ __forceinline__ void prop_bounds(
    float px1, float py1, float px2, float py2, float w, float h,
    float a, float ff,
    int& ox1, int& oy1, int& ox2, int& oy2)
{
    float n1 = floorf(__fadd_rn(px1, __fmul_rn(a, w)));
    float m1 = floorf(__fadd_rn(py1, __fmul_rn(a, h)));
    float n2 = ceilf (__fsub_rn(px2, __fmul_rn(a, w)));
    float m2 = ceilf (__fsub_rn(py2, __fmul_rn(a, h)));
    n2 = fminf(fmaxf(fmaxf(n2, n1 + 1.0f), 0.0f), ff);
    m2 = fminf(fmaxf(fmaxf(m2, m1 + 1.0f), 0.0f), ff);
    n1 = fminf(fmaxf(n1, 0.0f), ff - 1.0f);
    m1 = fminf(fmaxf(m1, 0.0f), ff - 1.0f);
    ox1 = (int)n1; oy1 = (int)m1; ox2 = (int)n2; oy2 = (int)m2;
}

__global__ void __launch_bounds__(256)
fsaf_all(const int* __restrict__ g_levels,
         const float* __restrict__ g_boxes,
         float* __restrict__ out)
{
    __shared__ GtEntry sh[MAXGT];
    __shared__ int s_n;
    __shared__ int s_u;
    __shared__ unsigned s_tick;

    const int tid  = threadIdx.x;
    const int lane = tid & 31;
    const int wid  = tid >> 5;

    int u = blockIdx.x;
    while (u < UNITS) {
        const int img = u / NTILES;
        const int bx  = u - img * NTILES;

        int lvl, tile;
        if      (bx < 64) { lvl = 0; tile = bx;      }
        else if (bx < 80) { lvl = 1; tile = bx - 64; }
        else if (bx < 84) { lvl = 2; tile = bx - 80; }
        else if (bx == 84){ lvl = 3; tile = 0;       }
        else              { lvl = 4; tile = 0;       }

        const int stride = 8 << lvl;
        const int f      = 128 >> lvl;
        const int lg     = 7 - lvl;
        const int hw     = f * f;
        const int cellOff = (lvl >= 1 ? 16384 : 0) + (lvl >= 2 ? 4096 : 0)
                          + (lvl >= 3 ? 1024  : 0) + (lvl >= 4 ? 256  : 0);

        // ---- Warp 0: compact GT data for (img,lvl) into shared (order-preserving).
        if (wid == 0) {
            int base = 0;
            #pragma unroll
            for (int half = 0; half < 2; ++half) {
                const int g = half * 32 + lane;
                const float* bp = g_boxes + ((size_t)img * MAXGT + g) * 5;
                float bx1 = bp[0], by1 = bp[1], bx2 = bp[2], by2 = bp[3];
                int   lab = (int)bp[4];
                bool  valid = (g_levels[img * MAXGT + g] == lvl);

                const float inv = 1.0f / (float)stride;   // exact (power of 2)
                float px1 = bx1 * inv, py1 = by1 * inv;
                float px2 = bx2 * inv, py2 = by2 * inv;
                float w = px2 - px1, h = py2 - py1;
                const float ff = (float)f;

                int pp1x, pp1y, pp2x, pp2y;   // POS_SCALE=0.2 -> a=0.4
                int ii1x, ii1y, ii2x, ii2y;   // IGNORE_SCALE=0.5 -> a=0.25
                prop_bounds(px1, py1, px2, py2, w, h, 0.4f,  ff, pp1x, pp1y, pp2x, pp2y);
                prop_bounds(px1, py1, px2, py2, w, h, 0.25f, ff, ii1x, ii1y, ii2x, ii2y);

                unsigned bm = __ballot_sync(0xffffffffu, valid);
                int pos = base + __popc(bm & ((1u << lane) - 1u));
                if (valid) {
                    GtEntry e;
                    e.pos = make_int4(pp1x, pp1y, pp2x, pp2y);
                    e.ign = make_int4(ii1x, ii1y, ii2x, ii2y);
                    e.uni = make_int4(min(pp1x, ii1x), min(pp1y, ii1y),
                                      max(pp2x, ii2x), max(pp2y, ii2y));
                    e.box = make_float4(bx1, by1, bx2, by2);
                    e.area = (bx2 - bx1) * (by2 - by1);
                    e.lab = lab; e.pad0 = 0; e.pad1 = 0;
                    sh[pos] = e;
                }
                base += __popc(bm);
            }
            if (lane == 0) s_n = base;
        }
        __syncthreads();
        const int n = s_n;

        // ---- Per-cell assignment (pure LDS+ALU; L1tex queue is empty here).
        const int cell    = tile * 256 + tid;
        const bool active = (cell < hw);
        const size_t imgCell = (size_t)img * HWTOT + cellOff + cell;
        const int y = cell >> lg;
        const int x = cell & (f - 1);

        const int cellW0 = tile * 256 + (wid << 5);
        const int ymin = cellW0 >> lg;
        const int ymax = (cellW0 + 31) >> lg;
        int xlo, xhi;
        if (ymin == ymax) { xlo = cellW0 & (f - 1); xhi = xlo + 31; }
        else              { xlo = 0;                xhi = f - 1;    }

        bool  anyp = false, anyi = false;
        float best = 1.0e10f;
        int   bidx = 0;

        for (int g = 0; g < n; ++g) {
            int4 uu = sh[g].uni;
            // Warp-uniform skip: does (pos U ign) bbox intersect warp range?
            if (uu.x <= xhi && uu.z > xlo && uu.y <= ymax && uu.w > ymin) {
                int4 pp = sh[g].pos;
                int4 ii = sh[g].ign;
                bool inp = (x >= pp.x) & (x < pp.z) & (y >= pp.y) & (y < pp.w);
                bool ini = (x >= ii.x) & (x < ii.z) & (y >= ii.y) & (y < ii.w);
                anyi |= ini;
                float a = sh[g].area;
                anyp |= inp;
                if (inp & (a < best)) { best = a; bidx = g; }  // strict < = first-index tie-break
            }
        }

        // ---- Store phase (all stores together, after compute).
        // num_pos: warp-aggregated exact integer count into device accumulator.
        unsigned pm = __ballot_sync(0xffffffffu, active && anyp);
        if (lane == 0 && pm)
            atomicAdd(&d_np[img], (float)__popc(pm));

        const int mylab = (active && anyp) ? sh[bidx].lab : -1;

        if (active) {
            out[OFF_CLS_M + imgCell] = (anyp || !anyi) ? 1.0f : 0.0f;
            out[OFF_REG_M + imgCell] = anyp ? 1.0f : 0.0f;

            float4 rv = make_float4(0.0f, 0.0f, 0.0f, 0.0f);
            if (anyp) {
                float4 cb = sh[bidx].box;
                float sx = ((float)x + 0.5f) * (float)stride;  // exact
                float sy = ((float)y + 0.5f) * (float)stride;
                rv.x = (sx - cb.x) * 0.25f;
                rv.y = (sy - cb.y) * 0.25f;
                rv.z = (cb.z - sx) * 0.25f;
                rv.w = (cb.w - sy) * 0.25f;
            }
            reinterpret_cast<float4*>(out + OFF_REG_T)[imgCell] = rv;
        }

        // cls_t: coalesced fill with the one-hot embedded via shuffle
        // (no second touch of the lines, no extra sync).
        if (cellW0 < hw) {   // hw multiple of 32 -> warp-uniform
            float4* basep = reinterpret_cast<float4*>(
                out + OFF_CLS_T + ((size_t)img * HWTOT + cellOff + cellW0) * NCLS);
            #pragma unroll
            for (int i = 0; i < 20; ++i) {
                int j  = i * 32 + lane;      // linear float4 index in 32x80 slab
                int cl = j / 20;             // local cell owning this float4
                int q  = j - cl * 20;        // quad index within that cell
                int hv = __shfl_sync(0xffffffffu, mylab, cl);
                float4 z = make_float4(0.0f, 0.0f, 0.0f, 0.0f);
                if (hv >= 0 && (hv >> 2) == q) {
                    int c = hv & 3;
                    z.x = (c == 0) ? 1.0f : 0.0f;
                    z.y = (c == 1) ? 1.0f : 0.0f;
                    z.z = (c == 2) ? 1.0f : 0.0f;
                    z.w = (c == 3) ? 1.0f : 0.0f;
                }
                basep[j] = z;
            }
        }

        // ---- Grab next unit (work stealing; also protects sh reuse).
        __syncthreads();
        if (tid == 0) s_u = (int)atomicAdd(&d_wctr, 1u);
        __syncthreads();
        u = s_u;
    }

    // ---- Completion ticket: last block finalizes num_pos and resets scratch.
    __threadfence();
    if (tid == 0) s_tick = atomicAdd(&d_ticket, 1u);
    __syncthreads();
    if (s_tick == GRID_MAIN - 1) {
        __threadfence();
        if (tid < BATCH) {
            float v = atomicAdd(&d_np[tid], 0.0f);   // L2-coherent read
            out[OFF_NP + tid] = v;
            d_np[tid] = 0.0f;                        // reset for next replay
        }
        if (tid == 0) {
            d_wctr   = GRID_MAIN;
            d_ticket = 0;
        }
    }
}

extern "C" void kernel_launch(void* const* d_in, const int* in_sizes, int n_in,
                              void* d_out, int out_size)
{
    const int*   levels = (const int*)  d_in[0];  // (16,64) int32
    const float* boxes  = (const float*)d_in[1];  // (16,64,5) float32
    float* out = (float*)d_out;

    fsaf_all<<<GRID_MAIN, 256>>>(levels, boxes, out);
}

// round 4
// speedup vs baseline: 1.0582x; 1.0582x over previous
#include <cuda_runtime.h>
#include <cstdint>

#define BATCH 16
#define MAXGT 64
#define NCLS 80
#define HWTOT 21824
#define NLVL 5
#define NTILES 86                 // tiles per image: 64+16+4+1+1
#define UNITS (NTILES * BATCH)    // 1376
#define GRID_MAIN 1184            // 8 blocks/SM * 148 SMs

// Output layout (floats), concatenated in reference return order.
#define OFF_CLS_T 0ULL
#define OFF_CLS_M ((size_t)BATCH * HWTOT * NCLS)            // 27,934,720
#define OFF_NP    (OFF_CLS_M + (size_t)BATCH * HWTOT)       // 28,283,904
#define OFF_REG_T (OFF_NP + BATCH)                          // 28,283,920
#define OFF_REG_M (OFF_REG_T + (size_t)BATCH * HWTOT * 4)   // 29,680,656

__device__ float    d_np[BATCH];        // zero-init; reset by finalizer each replay
__device__ unsigned d_ticket = 0;       // completion ticket; reset each replay

// Shrunken/clipped region bounds exactly like reference _prop_box.
// __f*_rn intrinsics forbid FMA contraction (floor/ceil boundary safety).
static __device__ __forceinline__ void prop_bounds(
    float px1, float py1, float px2, float py2, float w, float h,
    float a, float ff,
    int& ox1, int& oy1, int& ox2, int& oy2)
{
    float n1 = floorf(__fadd_rn(px1, __fmul_rn(a, w)));
    float m1 = floorf(__fadd_rn(py1, __fmul_rn(a, h)));
    float n2 = ceilf (__fsub_rn(px2, __fmul_rn(a, w)));
    float m2 = ceilf (__fsub_rn(py2, __fmul_rn(a, h)));
    n2 = fminf(fmaxf(fmaxf(n2, n1 + 1.0f), 0.0f), ff);
    m2 = fminf(fmaxf(fmaxf(m2, m1 + 1.0f), 0.0f), ff);
    n1 = fminf(fmaxf(n1, 0.0f), ff - 1.0f);
    m1 = fminf(fmaxf(m1, 0.0f), ff - 1.0f);
    ox1 = (int)n1; oy1 = (int)m1; ox2 = (int)n2; oy2 = (int)m2;
}

static __device__ __forceinline__ void decode_unit(int u, int& img, int& lvl, int& tile)
{
    img = u / NTILES;
    int bx = u - img * NTILES;
    if      (bx < 64) { lvl = 0; tile = bx;      }
    else if (bx < 80) { lvl = 1; tile = bx - 64; }
    else if (bx < 84) { lvl = 2; tile = bx - 80; }
    else if (bx == 84){ lvl = 3; tile = 0;       }
    else              { lvl = 4; tile = 0;       }
}

// Shared GT tables (double buffered), SoA.
struct SGt {
    int4   pos[MAXGT];
    int4   ign[MAXGT];
    int4   uni[MAXGT];
    float4 box[MAXGT];
    float  area[MAXGT];
    int    lab[MAXGT];
    int    n;
};

// Warp-0-only: compact GT data for (img,lvl) into shared buffer.
// Writes fields straight to shared (keeps register pressure low).
static __device__ __forceinline__ void compact_gts(
    SGt* s, const int* __restrict__ g_levels, const float* __restrict__ g_boxes,
    int img, int lvl, int lane)
{
    const int stride = 8 << lvl;
    const int f      = 128 >> lvl;
    const float ff   = (float)f;
    const float inv  = 1.0f / (float)stride;   // exact (power of 2)

    int base = 0;
    #pragma unroll
    for (int half = 0; half < 2; ++half) {
        const int g = half * 32 + lane;
        const float* bp = g_boxes + ((size_t)img * MAXGT + g) * 5;
        float bx1 = bp[0], by1 = bp[1], bx2 = bp[2], by2 = bp[3];
        int   lab = (int)bp[4];
        bool  valid = (g_levels[img * MAXGT + g] == lvl);

        float px1 = bx1 * inv, py1 = by1 * inv;
        float px2 = bx2 * inv, py2 = by2 * inv;
        float w = px2 - px1, h = py2 - py1;

        int pp1x, pp1y, pp2x, pp2y;   // POS_SCALE=0.2 -> a=0.4
        int ii1x, ii1y, ii2x, ii2y;   // IGNORE_SCALE=0.5 -> a=0.25
        prop_bounds(px1, py1, px2, py2, w, h, 0.4f,  ff, pp1x, pp1y, pp2x, pp2y);
        prop_bounds(px1, py1, px2, py2, w, h, 0.25f, ff, ii1x, ii1y, ii2x, ii2y);

        unsigned bm = __ballot_sync(0xffffffffu, valid);
        int pos = base + __popc(bm & ((1u << lane) - 1u));
        if (valid) {
            s->pos[pos] = make_int4(pp1x, pp1y, pp2x, pp2y);
            s->ign[pos] = make_int4(ii1x, ii1y, ii2x, ii2y);
            s->uni[pos] = make_int4(min(pp1x, ii1x), min(pp1y, ii1y),
                                    max(pp2x, ii2x), max(pp2y, ii2y));
            s->box[pos] = make_float4(bx1, by1, bx2, by2);
            s->area[pos] = (bx2 - bx1) * (by2 - by1);
            s->lab[pos] = lab;
        }
        base += __popc(bm);
    }
    if (lane == 0) s->n = base;
}

__global__ void __launch_bounds__(256)
fsaf_all(const int* __restrict__ g_levels,
         const float* __restrict__ g_boxes,
         float* __restrict__ out)
{
    __shared__ SGt sh[2];
    __shared__ unsigned s_tick;

    const int tid  = threadIdx.x;
    const int lane = tid & 31;
    const int wid  = tid >> 5;

    // ---- Prologue: compact GT table for the first unit.
    {
        int img, lvl, tile;
        decode_unit(blockIdx.x, img, lvl, tile);
        if (wid == 0) compact_gts(&sh[0], g_levels, g_boxes, img, lvl, lane);
    }
    __syncthreads();

    for (int it = 0, u = blockIdx.x; u < UNITS; ++it, u += GRID_MAIN) {
        int img, lvl, tile;
        decode_unit(u, img, lvl, tile);

        const int stride = 8 << lvl;
        const int f      = 128 >> lvl;
        const int lg     = 7 - lvl;
        const int hw     = f * f;
        const int cellOff = (lvl >= 1 ? 16384 : 0) + (lvl >= 2 ? 4096 : 0)
                          + (lvl >= 3 ? 1024  : 0) + (lvl >= 4 ? 256  : 0);

        const SGt* s = &sh[it & 1];
        const int n = s->n;

        // ---- Per-cell assignment (pure LDS+ALU; L1tex queue quiet here).
        const int cell    = tile * 256 + tid;
        const bool active = (cell < hw);
        const size_t imgCell = (size_t)img * HWTOT + cellOff + cell;
        const int y = cell >> lg;
        const int x = cell & (f - 1);

        const int cellW0 = tile * 256 + (wid << 5);
        const int ymin = cellW0 >> lg;
        const int ymax = (cellW0 + 31) >> lg;
        int xlo, xhi;
        if (ymin == ymax) { xlo = cellW0 & (f - 1); xhi = xlo + 31; }
        else              { xlo = 0;                xhi = f - 1;    }

        bool  anyp = false, anyi = false;
        float best = 1.0e10f;
        int   bidx = 0;

        for (int g = 0; g < n; ++g) {
            int4 uu = s->uni[g];   // LDS broadcast (warp-uniform address)
            if (uu.x <= xhi && uu.z > xlo && uu.y <= ymax && uu.w > ymin) {
                int4 pp = s->pos[g];
                int4 ii = s->ign[g];
                bool inp = (x >= pp.x) & (x < pp.z) & (y >= pp.y) & (y < pp.w);
                bool ini = (x >= ii.x) & (x < ii.z) & (y >= ii.y) & (y < ii.w);
                anyi |= ini;
                float a = s->area[g];
                anyp |= inp;
                if (inp & (a < best)) { best = a; bidx = g; }  // strict < = first-index tie-break
            }
        }

        // ---- Pipelined prefetch: compact NEXT unit's GT table now, while the
        // L1tex queue is still quiet; its LDGs complete under the store burst.
        {
            int un = u + GRID_MAIN;
            if (un < UNITS && wid == 0) {
                int nimg, nlvl, ntile;
                decode_unit(un, nimg, nlvl, ntile);
                compact_gts(&sh[(it + 1) & 1], g_levels, g_boxes, nimg, nlvl, lane);
            }
        }

        // ---- Store phase.
        // num_pos: warp-aggregated exact integer count into device accumulator.
        unsigned pm = __ballot_sync(0xffffffffu, active && anyp);
        if (lane == 0 && pm)
            atomicAdd(&d_np[img], (float)__popc(pm));

        if (active) {
            out[OFF_CLS_M + imgCell] = (anyp || !anyi) ? 1.0f : 0.0f;
            out[OFF_REG_M + imgCell] = anyp ? 1.0f : 0.0f;

            float4 rv = make_float4(0.0f, 0.0f, 0.0f, 0.0f);
            if (anyp) {
                float4 cb = s->box[bidx];
                float sx = ((float)x + 0.5f) * (float)stride;  // exact
                float sy = ((float)y + 0.5f) * (float)stride;
                rv.x = (sx - cb.x) * 0.25f;
                rv.y = (sy - cb.y) * 0.25f;
                rv.z = (cb.z - sx) * 0.25f;
                rv.w = (cb.w - sy) * 0.25f;
            }
            reinterpret_cast<float4*>(out + OFF_REG_T)[imgCell] = rv;
        }

        // cls_t: warp-cooperative coalesced zero fill (20 x STG.128 per warp),
        // then scatter the single one-hot element.
        if (cellW0 < hw) {   // hw multiple of 32 -> whole warp together
            float4* basep = reinterpret_cast<float4*>(
                out + OFF_CLS_T + ((size_t)img * HWTOT + cellOff + cellW0) * NCLS);
            const float4 z = make_float4(0.0f, 0.0f, 0.0f, 0.0f);
            #pragma unroll
            for (int i = 0; i < 20; ++i)
                basep[i * 32 + lane] = z;
            __syncwarp();
            if (anyp)
                out[OFF_CLS_T + imgCell * NCLS + s->lab[bidx]] = 1.0f;
        }

        // Barrier: (a) next iteration reads the prefetched buffer, (b) buffer
        // it&1 may be overwritten by the prefetch in iteration it+1.
        __syncthreads();
    }

    // ---- Completion ticket: last block finalizes num_pos, resets scratch.
    __threadfence();
    if (tid == 0) s_tick = atomicAdd(&d_ticket, 1u);
    __syncthreads();
    if (s_tick == GRID_MAIN - 1) {
        __threadfence();
        if (tid < BATCH) {
            float v = atomicAdd(&d_np[tid], 0.0f);   // coherent read
            out[OFF_NP + tid] = v;
            d_np[tid] = 0.0f;                        // reset for next replay
        }
        if (tid == 0) d_ticket = 0;
    }
}

extern "C" void kernel_launch(void* const* d_in, const int* in_sizes, int n_in,
                              void* d_out, int out_size)
{
    const int*   levels = (const int*)  d_in[0];  // (16,64) int32
    const float* boxes  = (const float*)d_in[1];  // (16,64,5) float32
    float* out = (float*)d_out;

    fsaf_all<<<GRID_MAIN, 256>>>(levels, boxes, out);
}